// round 1
// baseline (speedup 1.0000x reference)
#include <cuda_runtime.h>
#include <math.h>

// Problem constants (fixed shapes for OODDetectionHead_83708912599141)
#define BATCH   4096
#define NLEAF   50000
#define DIM     256
#define BM      128
#define BN      128
#define BKC     16
#define NCHUNK  18
#define NTILES  ((NLEAF + BN - 1) / BN)          // 391
#define TPC     ((NTILES + NCHUNK - 1) / NCHUNK) // 22
#define TOPT    8
#define NCAND   (NCHUNK * 128)                   // 2304 candidates per row
#define SHORTL  16
#define EPSF    1e-7f
#define PITCH   (BM + 4)                         // 132: 16B-aligned rows, de-conflicted

// Scratch (allocation-free: __device__ globals)
__device__ float g_x2[BATCH];
__device__ float g_y2[NLEAF];
__device__ float g_inv[NLEAF];                   // 1/(1 - y2)
__device__ float g_cval[(size_t)NCHUNK * BATCH * 128];
__device__ int   g_cidx[(size_t)NCHUNK * BATCH * 128];

// ---------------------------------------------------------------------------
// Kernel 1: squared norms for z rows and leaf rows (+ 1/(1-y2))
// warp per row; 8 dims per lane via two float4 loads
// ---------------------------------------------------------------------------
__global__ void prep_kernel(const float* __restrict__ X, const float* __restrict__ Y) {
    int warp = (blockIdx.x * blockDim.x + threadIdx.x) >> 5;
    int lane = threadIdx.x & 31;
    if (warp >= BATCH + NLEAF) return;
    const float* src = (warp < BATCH) ? (X + (size_t)warp * DIM)
                                      : (Y + (size_t)(warp - BATCH) * DIM);
    const float4* v = (const float4*)src;
    float4 a = v[lane * 2], b = v[lane * 2 + 1];
    float s = a.x*a.x + a.y*a.y + a.z*a.z + a.w*a.w
            + b.x*b.x + b.y*b.y + b.z*b.z + b.w*b.w;
    #pragma unroll
    for (int off = 16; off > 0; off >>= 1) s += __shfl_down_sync(0xffffffffu, s, off);
    if (lane == 0) {
        if (warp < BATCH) {
            g_x2[warp] = s;
        } else {
            int l = warp - BATCH;
            g_y2[l]  = s;
            g_inv[l] = 1.0f / (1.0f - s);
        }
    }
}

// ---------------------------------------------------------------------------
// Kernel 2: fused SGEMM + per-row top-8 (per thread) candidate selection.
// key = max(x2 + y2 - 2*xy, 0) / (1 - y2)  -- monotone in the hyperbolic
// distance per row (the 1/(1-x2) row factor is a positive constant).
// Block: 256 threads = 16x16, each 8x8 microtile of a 128x128 key tile.
// ---------------------------------------------------------------------------
__global__ void __launch_bounds__(256, 2)
main_kernel(const float* __restrict__ X, const float* __restrict__ Y) {
    __shared__ __align__(16) float Xs[BKC][PITCH];
    __shared__ __align__(16) float Ys[BKC][PITCH];

    const int tid = threadIdx.x;
    const int tx = tid & 15, ty = tid >> 4;
    const int rowblk = blockIdx.x, chunk = blockIdx.y;
    const int row0 = rowblk * BM;

    float tval[8][TOPT];
    int   tidx[8][TOPT];
    float tworst[8];
    #pragma unroll
    for (int i = 0; i < 8; i++) {
        #pragma unroll
        for (int s = 0; s < TOPT; s++) { tval[i][s] = INFINITY; tidx[i][s] = -1; }
        tworst[i] = INFINITY;
    }

    float x2r[8];
    #pragma unroll
    for (int i = 0; i < 8; i++) x2r[i] = g_x2[row0 + ty * 8 + i];

    const int t0 = chunk * TPC;
    const int t1 = (t0 + TPC < NTILES) ? (t0 + TPC) : NTILES;

    for (int t = t0; t < t1; t++) {
        const int col0 = t * BN;
        float acc[8][8];
        #pragma unroll
        for (int i = 0; i < 8; i++)
            #pragma unroll
            for (int j = 0; j < 8; j++) acc[i][j] = 0.0f;

        for (int kc = 0; kc < DIM / BKC; kc++) {
            // Load 128x16 tiles of X and Y, transposed into [k][m] layout.
            #pragma unroll
            for (int u = 0; u < 2; u++) {
                int s  = tid + u * 256;            // 0..511
                int r  = s >> 2;                   // 0..127
                int k4 = (s & 3) << 2;             // 0,4,8,12
                const float4 vx = *(const float4*)&X[(size_t)(row0 + r) * DIM + kc * BKC + k4];
                Xs[k4 + 0][r] = vx.x; Xs[k4 + 1][r] = vx.y;
                Xs[k4 + 2][r] = vx.z; Xs[k4 + 3][r] = vx.w;
                int col = col0 + r;
                float4 vy = make_float4(0.f, 0.f, 0.f, 0.f);
                if (col < NLEAF)
                    vy = *(const float4*)&Y[(size_t)col * DIM + kc * BKC + k4];
                Ys[k4 + 0][r] = vy.x; Ys[k4 + 1][r] = vy.y;
                Ys[k4 + 2][r] = vy.z; Ys[k4 + 3][r] = vy.w;
            }
            __syncthreads();
            #pragma unroll
            for (int k = 0; k < BKC; k++) {
                float4 a0 = *(const float4*)&Xs[k][ty * 8];
                float4 a1 = *(const float4*)&Xs[k][ty * 8 + 4];
                float4 b0 = *(const float4*)&Ys[k][tx * 8];
                float4 b1 = *(const float4*)&Ys[k][tx * 8 + 4];
                float a[8] = {a0.x, a0.y, a0.z, a0.w, a1.x, a1.y, a1.z, a1.w};
                float b[8] = {b0.x, b0.y, b0.z, b0.w, b1.x, b1.y, b1.z, b1.w};
                #pragma unroll
                for (int i = 0; i < 8; i++)
                    #pragma unroll
                    for (int j = 0; j < 8; j++)
                        acc[i][j] = fmaf(a[i], b[j], acc[i][j]);
            }
            __syncthreads();
        }

        // Fold this 128x128 key tile into per-thread top-8 lists.
        #pragma unroll
        for (int j = 0; j < 8; j++) {
            int col = col0 + tx * 8 + j;
            if (col >= NLEAF) continue;
            float y2  = g_y2[col];
            float inv = g_inv[col];
            #pragma unroll
            for (int i = 0; i < 8; i++) {
                float sq  = fmaxf(x2r[i] + y2 - 2.0f * acc[i][j], 0.0f);
                float key = sq * inv;
                if (key < tworst[i]) {
                    int p = TOPT - 1;
                    while (p > 0 && tval[i][p - 1] > key) {
                        tval[i][p] = tval[i][p - 1];
                        tidx[i][p] = tidx[i][p - 1];
                        p--;
                    }
                    tval[i][p] = key;
                    tidx[i][p] = col;
                    tworst[i] = tval[i][TOPT - 1];
                }
            }
        }
    }

    // Emit candidates: 128 per row per chunk (16 tx-threads x 8 entries).
    #pragma unroll
    for (int i = 0; i < 8; i++) {
        int r = row0 + ty * 8 + i;
        size_t base = ((size_t)chunk * BATCH + r) * 128 + tx * 8;
        #pragma unroll
        for (int s = 0; s < TOPT; s++) {
            g_cval[base + s] = tval[i][s];
            g_cidx[base + s] = tidx[i][s];
        }
    }
}

// ---------------------------------------------------------------------------
// Kernel 3: warp-per-row merge (2304 candidates -> top-16), exact fp32
// re-rank with the reference formula (incl. clamps), sort, write outputs.
// ---------------------------------------------------------------------------
__global__ void merge_kernel(const float* __restrict__ X, const float* __restrict__ Y,
                             const int* __restrict__ ids, const float* __restrict__ thr_p,
                             float* __restrict__ out, int out_size) {
    const int lane = threadIdx.x & 31;
    const int row = blockIdx.x * 8 + (threadIdx.x >> 5);
    if (row >= BATCH) return;
    const unsigned FULL = 0xffffffffu;

    // Per-lane sorted top-16 over its strided slice of the candidate list.
    float lv[SHORTL]; int li[SHORTL];
    #pragma unroll
    for (int s = 0; s < SHORTL; s++) { lv[s] = INFINITY; li[s] = 0x7fffffff; }
    for (int f = lane; f < NCAND; f += 32) {
        int chunk = f >> 7, slot = f & 127;
        size_t a = ((size_t)chunk * BATCH + row) * 128 + slot;
        float v = g_cval[a];
        if (v < lv[SHORTL - 1]) {
            int ix = g_cidx[a];
            int p = SHORTL - 1;
            while (p > 0 && (lv[p - 1] > v || (lv[p - 1] == v && li[p - 1] > ix))) {
                lv[p] = lv[p - 1]; li[p] = li[p - 1]; p--;
            }
            lv[p] = v; li[p] = ix;
        }
    }

    // Warp-wide selection of the global top-16 (lane r keeps the r-th pick).
    int head = 0;
    int seli = -1;
    for (int r = 0; r < SHORTL; r++) {
        float cv = (head < SHORTL) ? lv[head] : INFINITY;
        int   ci = (head < SHORTL) ? li[head] : 0x7fffffff;
        float bv = cv; int bi = ci; int bl = lane;
        #pragma unroll
        for (int off = 16; off > 0; off >>= 1) {
            float ov = __shfl_down_sync(FULL, bv, off);
            int   oi = __shfl_down_sync(FULL, bi, off);
            int   ol = __shfl_down_sync(FULL, bl, off);
            if (ov < bv || (ov == bv && oi < bi)) { bv = ov; bi = oi; bl = ol; }
        }
        bi = __shfl_sync(FULL, bi, 0);
        bl = __shfl_sync(FULL, bl, 0);
        if (lane == r)  seli = bi;
        if (lane == bl) head++;
    }

    // Exact re-rank: full fp32 reference formula per candidate.
    float x2 = g_x2[row];
    const float4* xr = (const float4*)(X + (size_t)row * DIM);
    float4 xa = xr[lane * 2], xb = xr[lane * 2 + 1];
    float my_dist = INFINITY;
    for (int c = 0; c < SHORTL; c++) {
        int ci = __shfl_sync(FULL, seli, c);      // warp-uniform
        float dist = INFINITY;
        if (ci >= 0 && ci < NLEAF) {
            const float4* yr = (const float4*)(Y + (size_t)ci * DIM);
            float4 ya = yr[lane * 2], yb = yr[lane * 2 + 1];
            float s = xa.x*ya.x + xa.y*ya.y + xa.z*ya.z + xa.w*ya.w
                    + xb.x*yb.x + xb.y*yb.y + xb.z*yb.z + xb.w*yb.w;
            #pragma unroll
            for (int off = 16; off > 0; off >>= 1) s += __shfl_down_sync(FULL, s, off);
            s = __shfl_sync(FULL, s, 0);
            float y2 = g_y2[ci];
            float sq    = fmaxf(x2 + y2 - 2.0f * s, 0.0f);
            float denom = fmaxf((1.0f - x2) * (1.0f - y2), EPSF);
            float arg   = fmaxf(1.0f + 2.0f * sq / denom, 1.0f + EPSF);
            dist = acoshf(arg);
        } else {
            ci = -1;
        }
        if (lane == c) { my_dist = dist; seli = ci; }
    }

    // Gather (dist, idx) pairs and sort ascending by (dist, idx).
    float dall[SHORTL]; int iall[SHORTL];
    for (int c = 0; c < SHORTL; c++) {
        dall[c] = __shfl_sync(FULL, my_dist, c);
        iall[c] = __shfl_sync(FULL, seli, c);
    }
    for (int a = 1; a < SHORTL; a++) {
        float dv = dall[a]; int iv = iall[a];
        int p = a;
        while (p > 0 && (dall[p - 1] > dv || (dall[p - 1] == dv && iall[p - 1] > iv))) {
            dall[p] = dall[p - 1]; iall[p] = iall[p - 1]; p--;
        }
        dall[p] = dv; iall[p] = iv;
    }

    if (lane == 0) {
        float score = dall[0];
        out[row] = score;
        if (out_size >= 2 * BATCH)
            out[BATCH + row] = (score > thr_p[0]) ? 1.0f : 0.0f;
        if (out_size >= 7 * BATCH) {
            #pragma unroll
            for (int j = 0; j < 5; j++) {
                int ci = iall[j];
                int id = (ci >= 0) ? ids[ci] : 0;
                out[2 * BATCH + (size_t)row * 5 + j] = (float)id;
            }
        }
    }
}

// ---------------------------------------------------------------------------
extern "C" void kernel_launch(void* const* d_in, const int* in_sizes, int n_in,
                              void* d_out, int out_size) {
    const float* X   = (const float*)d_in[0];   // z_hyp    (4096, 256)
    const float* Y   = (const float*)d_in[1];   // leaf_emb (50000, 256)
    const int*   ids = (const int*)d_in[2];     // leaf_node_ids (50000,)
    const float* thr = (const float*)d_in[3];   // threshold scalar
    float* out = (float*)d_out;

    int prep_warps = BATCH + NLEAF;
    prep_kernel<<<(prep_warps + 7) / 8, 256>>>(X, Y);

    dim3 grid(BATCH / BM, NCHUNK);
    main_kernel<<<grid, 256>>>(X, Y);

    merge_kernel<<<BATCH / 8, 256>>>(X, Y, ids, thr, out, out_size);
}

// round 2
// speedup vs baseline: 1.0022x; 1.0022x over previous
#include <cuda_runtime.h>
#include <math.h>

// Problem constants (fixed shapes for OODDetectionHead_83708912599141)
#define BATCH   4096
#define NLEAF   50000
#define DIM     256
#define BM      128
#define BN      128
#define BKC     16
#define NCHUNK  18
#define NTILES  ((NLEAF + BN - 1) / BN)          // 391
#define TPC     ((NTILES + NCHUNK - 1) / NCHUNK) // 22
#define TOPT    8
#define NCAND   (NCHUNK * 128)                   // 2304 candidates per row
#define SHORTL  16
#define EPSF    1e-7f
#define PITCH   (BM + 4)                         // 132: 16B-aligned rows, de-conflicted

// Scratch (allocation-free: __device__ globals)
__device__ float g_x2[BATCH];
__device__ float g_y2[NLEAF];
__device__ float g_inv[NLEAF];                   // 1/(1 - y2)
__device__ float g_cval[(size_t)NCHUNK * BATCH * 128];
__device__ int   g_cidx[(size_t)NCHUNK * BATCH * 128];

// ---------------------------------------------------------------------------
// Kernel 1: squared norms for z rows and leaf rows (+ 1/(1-y2))
// warp per row; 8 dims per lane via two float4 loads
// ---------------------------------------------------------------------------
__global__ void prep_kernel(const float* __restrict__ X, const float* __restrict__ Y) {
    int warp = (blockIdx.x * blockDim.x + threadIdx.x) >> 5;
    int lane = threadIdx.x & 31;
    if (warp >= BATCH + NLEAF) return;
    const float* src = (warp < BATCH) ? (X + (size_t)warp * DIM)
                                      : (Y + (size_t)(warp - BATCH) * DIM);
    const float4* v = (const float4*)src;
    float4 a = v[lane * 2], b = v[lane * 2 + 1];
    float s = a.x*a.x + a.y*a.y + a.z*a.z + a.w*a.w
            + b.x*b.x + b.y*b.y + b.z*b.z + b.w*b.w;
    #pragma unroll
    for (int off = 16; off > 0; off >>= 1) s += __shfl_down_sync(0xffffffffu, s, off);
    if (lane == 0) {
        if (warp < BATCH) {
            g_x2[warp] = s;
        } else {
            int l = warp - BATCH;
            g_y2[l]  = s;
            g_inv[l] = 1.0f / (1.0f - s);
        }
    }
}

// ---------------------------------------------------------------------------
// Kernel 2: fused SGEMM + per-row top-8 (per thread) candidate selection.
// key = max(x2 + y2 - 2*xy, 0) / (1 - y2)  -- monotone in the hyperbolic
// distance per row (the 1/(1-x2) row factor is a positive constant).
// Block: 256 threads = 16x16, each 8x8 microtile of a 128x128 key tile.
// ---------------------------------------------------------------------------
__global__ void __launch_bounds__(256, 2)
main_kernel(const float* __restrict__ X, const float* __restrict__ Y) {
    __shared__ __align__(16) float Xs[BKC][PITCH];
    __shared__ __align__(16) float Ys[BKC][PITCH];

    const int tid = threadIdx.x;
    const int tx = tid & 15, ty = tid >> 4;
    const int rowblk = blockIdx.x, chunk = blockIdx.y;
    const int row0 = rowblk * BM;

    float tval[8][TOPT];
    int   tidx[8][TOPT];
    float tworst[8];
    #pragma unroll
    for (int i = 0; i < 8; i++) {
        #pragma unroll
        for (int s = 0; s < TOPT; s++) { tval[i][s] = INFINITY; tidx[i][s] = -1; }
        tworst[i] = INFINITY;
    }

    float x2r[8];
    #pragma unroll
    for (int i = 0; i < 8; i++) x2r[i] = g_x2[row0 + ty * 8 + i];

    const int t0 = chunk * TPC;
    const int t1 = (t0 + TPC < NTILES) ? (t0 + TPC) : NTILES;

    for (int t = t0; t < t1; t++) {
        const int col0 = t * BN;
        float acc[8][8];
        #pragma unroll
        for (int i = 0; i < 8; i++)
            #pragma unroll
            for (int j = 0; j < 8; j++) acc[i][j] = 0.0f;

        for (int kc = 0; kc < DIM / BKC; kc++) {
            // Load 128x16 tiles of X and Y, transposed into [k][m] layout.
            #pragma unroll
            for (int u = 0; u < 2; u++) {
                int s  = tid + u * 256;            // 0..511
                int r  = s >> 2;                   // 0..127
                int k4 = (s & 3) << 2;             // 0,4,8,12
                const float4 vx = *(const float4*)&X[(size_t)(row0 + r) * DIM + kc * BKC + k4];
                Xs[k4 + 0][r] = vx.x; Xs[k4 + 1][r] = vx.y;
                Xs[k4 + 2][r] = vx.z; Xs[k4 + 3][r] = vx.w;
                int col = col0 + r;
                float4 vy = make_float4(0.f, 0.f, 0.f, 0.f);
                if (col < NLEAF)
                    vy = *(const float4*)&Y[(size_t)col * DIM + kc * BKC + k4];
                Ys[k4 + 0][r] = vy.x; Ys[k4 + 1][r] = vy.y;
                Ys[k4 + 2][r] = vy.z; Ys[k4 + 3][r] = vy.w;
            }
            __syncthreads();
            #pragma unroll
            for (int k = 0; k < BKC; k++) {
                float4 a0 = *(const float4*)&Xs[k][ty * 8];
                float4 a1 = *(const float4*)&Xs[k][ty * 8 + 4];
                float4 b0 = *(const float4*)&Ys[k][tx * 8];
                float4 b1 = *(const float4*)&Ys[k][tx * 8 + 4];
                float a[8] = {a0.x, a0.y, a0.z, a0.w, a1.x, a1.y, a1.z, a1.w};
                float b[8] = {b0.x, b0.y, b0.z, b0.w, b1.x, b1.y, b1.z, b1.w};
                #pragma unroll
                for (int i = 0; i < 8; i++)
                    #pragma unroll
                    for (int j = 0; j < 8; j++)
                        acc[i][j] = fmaf(a[i], b[j], acc[i][j]);
            }
            __syncthreads();
        }

        // Fold this 128x128 key tile into per-thread top-8 lists.
        #pragma unroll
        for (int j = 0; j < 8; j++) {
            int col = col0 + tx * 8 + j;
            if (col >= NLEAF) continue;
            float y2  = g_y2[col];
            float inv = g_inv[col];
            #pragma unroll
            for (int i = 0; i < 8; i++) {
                float sq  = fmaxf(x2r[i] + y2 - 2.0f * acc[i][j], 0.0f);
                float key = sq * inv;
                if (key < tworst[i]) {
                    int p = TOPT - 1;
                    while (p > 0 && tval[i][p - 1] > key) {
                        tval[i][p] = tval[i][p - 1];
                        tidx[i][p] = tidx[i][p - 1];
                        p--;
                    }
                    tval[i][p] = key;
                    tidx[i][p] = col;
                    tworst[i] = tval[i][TOPT - 1];
                }
            }
        }
    }

    // Emit candidates: 128 per row per chunk (16 tx-threads x 8 entries).
    #pragma unroll
    for (int i = 0; i < 8; i++) {
        int r = row0 + ty * 8 + i;
        size_t base = ((size_t)chunk * BATCH + r) * 128 + tx * 8;
        #pragma unroll
        for (int s = 0; s < TOPT; s++) {
            g_cval[base + s] = tval[i][s];
            g_cidx[base + s] = tidx[i][s];
        }
    }
}

// ---------------------------------------------------------------------------
// Kernel 3: warp-per-row merge (2304 candidates -> top-16), exact fp32
// re-rank with the reference formula (incl. clamps), sort, write outputs.
// ---------------------------------------------------------------------------
__global__ void merge_kernel(const float* __restrict__ X, const float* __restrict__ Y,
                             const int* __restrict__ ids, const float* __restrict__ thr_p,
                             float* __restrict__ out, int out_size) {
    const int lane = threadIdx.x & 31;
    const int row = blockIdx.x * 8 + (threadIdx.x >> 5);
    if (row >= BATCH) return;
    const unsigned FULL = 0xffffffffu;

    // Per-lane sorted top-16 over its strided slice of the candidate list.
    float lv[SHORTL]; int li[SHORTL];
    #pragma unroll
    for (int s = 0; s < SHORTL; s++) { lv[s] = INFINITY; li[s] = 0x7fffffff; }
    for (int f = lane; f < NCAND; f += 32) {
        int chunk = f >> 7, slot = f & 127;
        size_t a = ((size_t)chunk * BATCH + row) * 128 + slot;
        float v = g_cval[a];
        if (v < lv[SHORTL - 1]) {
            int ix = g_cidx[a];
            int p = SHORTL - 1;
            while (p > 0 && (lv[p - 1] > v || (lv[p - 1] == v && li[p - 1] > ix))) {
                lv[p] = lv[p - 1]; li[p] = li[p - 1]; p--;
            }
            lv[p] = v; li[p] = ix;
        }
    }

    // Warp-wide selection of the global top-16 (lane r keeps the r-th pick).
    int head = 0;
    int seli = -1;
    for (int r = 0; r < SHORTL; r++) {
        float cv = (head < SHORTL) ? lv[head] : INFINITY;
        int   ci = (head < SHORTL) ? li[head] : 0x7fffffff;
        float bv = cv; int bi = ci; int bl = lane;
        #pragma unroll
        for (int off = 16; off > 0; off >>= 1) {
            float ov = __shfl_down_sync(FULL, bv, off);
            int   oi = __shfl_down_sync(FULL, bi, off);
            int   ol = __shfl_down_sync(FULL, bl, off);
            if (ov < bv || (ov == bv && oi < bi)) { bv = ov; bi = oi; bl = ol; }
        }
        bi = __shfl_sync(FULL, bi, 0);
        bl = __shfl_sync(FULL, bl, 0);
        if (lane == r)  seli = bi;
        if (lane == bl) head++;
    }

    // Exact re-rank: full fp32 reference formula per candidate.
    float x2 = g_x2[row];
    const float4* xr = (const float4*)(X + (size_t)row * DIM);
    float4 xa = xr[lane * 2], xb = xr[lane * 2 + 1];
    float my_dist = INFINITY;
    for (int c = 0; c < SHORTL; c++) {
        int ci = __shfl_sync(FULL, seli, c);      // warp-uniform
        float dist = INFINITY;
        if (ci >= 0 && ci < NLEAF) {
            const float4* yr = (const float4*)(Y + (size_t)ci * DIM);
            float4 ya = yr[lane * 2], yb = yr[lane * 2 + 1];
            float s = xa.x*ya.x + xa.y*ya.y + xa.z*ya.z + xa.w*ya.w
                    + xb.x*yb.x + xb.y*yb.y + xb.z*yb.z + xb.w*yb.w;
            #pragma unroll
            for (int off = 16; off > 0; off >>= 1) s += __shfl_down_sync(FULL, s, off);
            s = __shfl_sync(FULL, s, 0);
            float y2 = g_y2[ci];
            float sq    = fmaxf(x2 + y2 - 2.0f * s, 0.0f);
            float denom = fmaxf((1.0f - x2) * (1.0f - y2), EPSF);
            float arg   = fmaxf(1.0f + 2.0f * sq / denom, 1.0f + EPSF);
            dist = acoshf(arg);
        } else {
            ci = -1;
        }
        if (lane == c) { my_dist = dist; seli = ci; }
    }

    // Gather (dist, idx) pairs and sort ascending by (dist, idx).
    float dall[SHORTL]; int iall[SHORTL];
    for (int c = 0; c < SHORTL; c++) {
        dall[c] = __shfl_sync(FULL, my_dist, c);
        iall[c] = __shfl_sync(FULL, seli, c);
    }
    for (int a = 1; a < SHORTL; a++) {
        float dv = dall[a]; int iv = iall[a];
        int p = a;
        while (p > 0 && (dall[p - 1] > dv || (dall[p - 1] == dv && iall[p - 1] > iv))) {
            dall[p] = dall[p - 1]; iall[p] = iall[p - 1]; p--;
        }
        dall[p] = dv; iall[p] = iv;
    }

    if (lane == 0) {
        float score = dall[0];
        out[row] = score;
        if (out_size >= 2 * BATCH)
            out[BATCH + row] = (score > thr_p[0]) ? 1.0f : 0.0f;
        if (out_size >= 7 * BATCH) {
            #pragma unroll
            for (int j = 0; j < 5; j++) {
                int ci = iall[j];
                int id = (ci >= 0) ? ids[ci] : 0;
                out[2 * BATCH + (size_t)row * 5 + j] = (float)id;
            }
        }
    }
}

// ---------------------------------------------------------------------------
extern "C" void kernel_launch(void* const* d_in, const int* in_sizes, int n_in,
                              void* d_out, int out_size) {
    const float* X   = (const float*)d_in[0];   // z_hyp    (4096, 256)
    const float* Y   = (const float*)d_in[1];   // leaf_emb (50000, 256)
    const int*   ids = (const int*)d_in[2];     // leaf_node_ids (50000,)
    const float* thr = (const float*)d_in[3];   // threshold scalar
    float* out = (float*)d_out;

    int prep_warps = BATCH + NLEAF;
    prep_kernel<<<(prep_warps + 7) / 8, 256>>>(X, Y);

    dim3 grid(BATCH / BM, NCHUNK);
    main_kernel<<<grid, 256>>>(X, Y);

    merge_kernel<<<BATCH / 8, 256>>>(X, Y, ids, thr, out, out_size);
}

// round 4
// speedup vs baseline: 4.8424x; 4.8320x over previous
#include <cuda_runtime.h>
#include <cuda_bf16.h>
#include <cstdint>
#include <math.h>

#define BATCH   4096
#define NLEAF   50000
#define DIM     256
#define KPAD    288                 // 256 dims + 2 aug + zero pad (18 ksteps of 16)
#define CHUNKL  5556
#define NCHUNK  9
#define NTILES  44                  // tiles of 128 leaves per chunk
#define EPSF    1e-7f
#define SHORTL  16
#define NSLOT   5
#define NCANDR  (NCHUNK * NSLOT)    // 45 candidates per row

// smem layout: 2 stages of {Ahi,Alo,Bhi,Blo} each 128 rows x 112B, + dump
#define PITCHB   112
#define MATB     (128 * PITCHB)     // 14336
#define OFF_ALO  MATB
#define OFF_BHI  (2 * MATB)
#define OFF_BLO  (3 * MATB)
#define STAGEB   (4 * MATB)         // 57344
#define OFF_DUMP (2 * STAGEB)       // 114688
#define DPITCH   132                // floats; pitch*4 % 128 == 16 -> conflict-lean
#define SMEM_TOTAL (OFF_DUMP + 128 * DPITCH * 4)   // 182272

__device__ float g_x2[BATCH];
__device__ float g_y2[NLEAF];
__device__ __align__(16) __nv_bfloat16 g_Xh[(size_t)BATCH * KPAD];
__device__ __align__(16) __nv_bfloat16 g_Xl[(size_t)BATCH * KPAD];
__device__ __align__(16) __nv_bfloat16 g_Yh[(size_t)NLEAF * KPAD];
__device__ __align__(16) __nv_bfloat16 g_Yl[(size_t)NLEAF * KPAD];
__device__ float g_cval[(size_t)NCHUNK * BATCH * NSLOT];
__device__ int   g_cidx[(size_t)NCHUNK * BATCH * NSLOT];

__device__ __forceinline__ uint32_t smem_to_u32(const void* p) {
    uint32_t a;
    asm("{ .reg .u64 t; cvta.to.shared.u64 t, %1; cvt.u32.u64 %0, t; }" : "=r"(a) : "l"(p));
    return a;
}
#define LDSM_X4(r0, r1, r2, r3, addr) \
    asm volatile("ldmatrix.sync.aligned.m8n8.x4.shared.b16 {%0,%1,%2,%3}, [%4];" \
        : "=r"(r0), "=r"(r1), "=r"(r2), "=r"(r3) : "r"(addr))
#define MMA16816(c, a, b0, b1) \
    asm volatile("mma.sync.aligned.m16n8k16.row.col.f32.bf16.bf16.f32 " \
        "{%0,%1,%2,%3},{%4,%5,%6,%7},{%8,%9},{%0,%1,%2,%3};" \
        : "+f"((c)[0]), "+f"((c)[1]), "+f"((c)[2]), "+f"((c)[3]) \
        : "r"((a)[0]), "r"((a)[1]), "r"((a)[2]), "r"((a)[3]), "r"(b0), "r"(b1))
#define CP_WAIT(n) asm volatile("cp.async.wait_group %0;" :: "n"(n) : "memory")

__device__ __forceinline__ unsigned bfu(__nv_bfloat16 h) {
    return (unsigned)__bfloat16_as_ushort(h);
}

// ---------------- Kernel 1: norms + bf16 hi/lo split of augmented rows ----
// x' = [x, x2, 1, 0pad];  y' = [-2*inv*y, inv, y2*inv, 0pad], inv=1/(1-y2)
// => dot(x', y') = (x2 + y2 - 2 x.y)/(1 - y2): monotone hyperbolic-dist key.
__global__ void prep_kernel(const float* __restrict__ X, const float* __restrict__ Y) {
    int warp = (blockIdx.x * blockDim.x + threadIdx.x) >> 5;
    int lane = threadIdx.x & 31;
    if (warp >= BATCH + NLEAF) return;
    bool isX = warp < BATCH;
    int row = isX ? warp : warp - BATCH;
    const float* src = (isX ? X : Y) + (size_t)row * DIM;
    float4 a = ((const float4*)src)[lane * 2];
    float4 b = ((const float4*)src)[lane * 2 + 1];
    float v[8] = {a.x, a.y, a.z, a.w, b.x, b.y, b.z, b.w};
    float s = 0.0f;
    #pragma unroll
    for (int i = 0; i < 8; i++) s += v[i] * v[i];
    #pragma unroll
    for (int o = 16; o; o >>= 1) s += __shfl_xor_sync(0xffffffffu, s, o);

    float scale, aug0, aug1;
    __nv_bfloat16 *dh, *dl;
    if (isX) {
        if (lane == 0) g_x2[row] = s;
        scale = 1.0f; aug0 = s; aug1 = 1.0f;
        dh = g_Xh + (size_t)row * KPAD; dl = g_Xl + (size_t)row * KPAD;
    } else {
        float inv = 1.0f / (1.0f - s);
        if (lane == 0) g_y2[row] = s;
        scale = -2.0f * inv; aug0 = inv; aug1 = s * inv;
        dh = g_Yh + (size_t)row * KPAD; dl = g_Yl + (size_t)row * KPAD;
    }
    unsigned hw[4], lw[4];
    #pragma unroll
    for (int i = 0; i < 4; i++) {
        float w0 = v[2*i] * scale, w1 = v[2*i+1] * scale;
        __nv_bfloat16 h0 = __float2bfloat16(w0), h1 = __float2bfloat16(w1);
        float r0 = w0 - __bfloat162float(h0), r1 = w1 - __bfloat162float(h1);
        hw[i] = bfu(h0) | (bfu(h1) << 16);
        lw[i] = bfu(__float2bfloat16(r0)) | (bfu(__float2bfloat16(r1)) << 16);
    }
    ((uint4*)dh)[lane] = make_uint4(hw[0], hw[1], hw[2], hw[3]);
    ((uint4*)dl)[lane] = make_uint4(lw[0], lw[1], lw[2], lw[3]);
    if (lane == 0) {
        __nv_bfloat16 h0 = __float2bfloat16(aug0), h1 = __float2bfloat16(aug1);
        float r0 = aug0 - __bfloat162float(h0), r1 = aug1 - __bfloat162float(h1);
        uint4 z = make_uint4(0, 0, 0, 0);
        ((uint4*)dh)[32] = make_uint4(bfu(h0) | (bfu(h1) << 16), 0, 0, 0);
        ((uint4*)dl)[32] = make_uint4(bfu(__float2bfloat16(r0)) | (bfu(__float2bfloat16(r1)) << 16), 0, 0, 0);
        #pragma unroll
        for (int q = 33; q < 36; q++) { ((uint4*)dh)[q] = z; ((uint4*)dl)[q] = z; }
    }
}

// cp.async one k-chunk (48 k-elems) of Ahi/Alo/Bhi/Blo into one smem stage
__device__ __forceinline__ void issue_loads(uint32_t stg, int tid, int mrow0,
                                            int leaf0, int kc) {
    const int k0 = kc * 48;
    #pragma unroll
    for (int i = 0; i < 24; i++) {
        int u = tid + 128 * i;
        int mat = u / 768;                 // constant per unrolled i
        int rem = u - mat * 768;
        int row = rem / 6;
        int col = rem - row * 6;
        uint32_t dst = stg + (uint32_t)mat * MATB + (uint32_t)row * PITCHB
                     + (uint32_t)col * 16;
        const __nv_bfloat16* src;
        if (mat < 2) {
            src = (mat == 0 ? g_Xh : g_Xl) + (size_t)(mrow0 + row) * KPAD + k0 + col * 8;
        } else {
            int leaf = leaf0 + row; if (leaf >= NLEAF) leaf = NLEAF - 1;
            src = (mat == 2 ? g_Yh : g_Yl) + (size_t)leaf * KPAD + k0 + col * 8;
        }
        asm volatile("cp.async.cg.shared.global [%0], [%1], 16;"
                     :: "r"(dst), "l"(src) : "memory");
    }
    asm volatile("cp.async.commit_group;" ::: "memory");
}

// ---------------- Kernel 2: bf16x3 mma.sync GEMM + fused exact top-5 ------
// 128 threads = 4 warps (2x2), warp tile 64x64, block tile 128x128, K=288.
__global__ void __launch_bounds__(128) main_kernel() {
    extern __shared__ char smem[];
    const uint32_t sb = smem_to_u32(smem);
    const int tid = threadIdx.x, lane = tid & 31, w = tid >> 5;
    const int wm = w >> 1, wn = w & 1;
    const int mblk = blockIdx.x, chunk = blockIdx.y;
    const int mrow0 = mblk * 128;
    const int leaf_base = chunk * CHUNKL;
    int leaf_end = leaf_base + CHUNKL; if (leaf_end > NLEAF) leaf_end = NLEAF;

    // per-lane ldmatrix address components (16B aligned everywhere)
    const uint32_t aoff = (uint32_t)(wm * 64 + (lane & 15)) * PITCHB
                        + ((lane >> 4) & 1) * 16;
    const uint32_t boff = (uint32_t)(wn * 64 + (lane & 7) + ((lane >> 4) & 1) * 8) * PITCHB
                        + ((lane >> 3) & 1) * 16;

    float tv[NSLOT]; int ti[NSLOT];
    #pragma unroll
    for (int q = 0; q < NSLOT; q++) { tv[q] = INFINITY; ti[q] = -1; }

    for (int t = 0; t < NTILES; t++) {
        const int leaf0 = leaf_base + t * 128;
        issue_loads(sb, tid, mrow0, leaf0, 0);

        float c[4][8][4];
        #pragma unroll
        for (int mi = 0; mi < 4; mi++)
            #pragma unroll
            for (int ni = 0; ni < 8; ni++)
                #pragma unroll
                for (int e = 0; e < 4; e++) c[mi][ni][e] = 0.0f;

        for (int kc = 0; kc < 6; kc++) {
            const uint32_t stg = sb + (uint32_t)(kc & 1) * STAGEB;
            if (kc < 5) {
                issue_loads(sb + (uint32_t)((kc + 1) & 1) * STAGEB, tid, mrow0, leaf0, kc + 1);
                CP_WAIT(1);
            } else {
                CP_WAIT(0);
            }
            __syncthreads();

            #pragma unroll
            for (int pass = 0; pass < 3; pass++) {
                const uint32_t Ab = stg + (pass == 2 ? OFF_ALO : 0u) + aoff;
                const uint32_t Bb = stg + (pass == 1 ? (uint32_t)OFF_BLO : (uint32_t)OFF_BHI) + boff;
                #pragma unroll
                for (int ks = 0; ks < 3; ks++) {
                    uint32_t a[4][4];
                    #pragma unroll
                    for (int mi = 0; mi < 4; mi++)
                        LDSM_X4(a[mi][0], a[mi][1], a[mi][2], a[mi][3],
                                Ab + mi * (16 * PITCHB) + ks * 32);
                    #pragma unroll
                    for (int nj = 0; nj < 4; nj++) {
                        uint32_t b[4];
                        LDSM_X4(b[0], b[1], b[2], b[3],
                                Bb + nj * (16 * PITCHB) + ks * 32);
                        #pragma unroll
                        for (int mi = 0; mi < 4; mi++) {
                            MMA16816(c[mi][2 * nj],     a[mi], b[0], b[1]);
                            MMA16816(c[mi][2 * nj + 1], a[mi], b[2], b[3]);
                        }
                    }
                }
            }
            __syncthreads();
        }

        // dump accum (128x128 f32) to smem, row-uniform
        {
            const uint32_t dmp = sb + OFF_DUMP;
            const int r0 = wm * 64 + (lane >> 2);
            const int c0 = wn * 64 + 2 * (lane & 3);
            #pragma unroll
            for (int mi = 0; mi < 4; mi++) {
                #pragma unroll
                for (int ni = 0; ni < 8; ni++) {
                    uint32_t a0 = dmp + (uint32_t)((r0 + mi * 16) * DPITCH + c0 + ni * 8) * 4;
                    asm volatile("st.shared.v2.f32 [%0], {%1,%2};"
                                 :: "r"(a0), "f"(c[mi][ni][0]), "f"(c[mi][ni][1]) : "memory");
                    asm volatile("st.shared.v2.f32 [%0], {%1,%2};"
                                 :: "r"(a0 + 8 * DPITCH * 4), "f"(c[mi][ni][2]), "f"(c[mi][ni][3]) : "memory");
                }
            }
        }
        __syncthreads();
        // thread tid owns row tid: exact top-5 over this tile's 128 cols
        {
            int nvalid = leaf_end - leaf0; if (nvalid > 128) nvalid = 128;
            const uint32_t rb = sb + OFF_DUMP + (uint32_t)tid * (DPITCH * 4);
            #pragma unroll 4
            for (int j4 = 0; j4 < 32; j4++) {
                float v0, v1, v2, v3;
                asm volatile("ld.shared.v4.f32 {%0,%1,%2,%3}, [%4];"
                             : "=f"(v0), "=f"(v1), "=f"(v2), "=f"(v3)
                             : "r"(rb + j4 * 16));
                float vv[4] = {v0, v1, v2, v3};
                #pragma unroll
                for (int e = 0; e < 4; e++) {
                    int col = j4 * 4 + e;
                    float key = fmaxf(vv[e], 0.0f);
                    if (col < nvalid && key < tv[4]) {
                        tv[4] = key; ti[4] = leaf0 + col;
                        #pragma unroll
                        for (int q = 4; q > 0; q--) {
                            if (tv[q] < tv[q - 1]) {
                                float fv = tv[q]; tv[q] = tv[q - 1]; tv[q - 1] = fv;
                                int iv = ti[q]; ti[q] = ti[q - 1]; ti[q - 1] = iv;
                            }
                        }
                    }
                }
            }
        }
        __syncthreads();
    }

    const int grow = mrow0 + tid;
    const size_t cb = ((size_t)chunk * BATCH + grow) * NSLOT;
    #pragma unroll
    for (int q = 0; q < NSLOT; q++) { g_cval[cb + q] = tv[q]; g_cidx[cb + q] = ti[q]; }
}

// ---------------- Kernel 3: merge 45 cands -> top-16, exact re-rank -------
__global__ void merge_kernel(const float* __restrict__ X, const float* __restrict__ Y,
                             const int* __restrict__ ids, const float* __restrict__ thr_p,
                             float* __restrict__ out, int out_size) {
    const int lane = threadIdx.x & 31;
    const int row = blockIdx.x * 8 + (threadIdx.x >> 5);
    if (row >= BATCH) return;
    const unsigned FULL = 0xffffffffu;

    float lv[SHORTL]; int li[SHORTL];
    #pragma unroll
    for (int s = 0; s < SHORTL; s++) { lv[s] = INFINITY; li[s] = 0x7fffffff; }
    for (int f = lane; f < NCANDR; f += 32) {
        int ch = f / NSLOT, slot = f - ch * NSLOT;
        size_t a = ((size_t)ch * BATCH + row) * NSLOT + slot;
        float v = g_cval[a];
        if (v < lv[SHORTL - 1]) {
            int ix = g_cidx[a];
            int p = SHORTL - 1;
            while (p > 0 && (lv[p-1] > v || (lv[p-1] == v && li[p-1] > ix))) {
                lv[p] = lv[p-1]; li[p] = li[p-1]; p--;
            }
            lv[p] = v; li[p] = ix;
        }
    }

    int head = 0, seli = -1;
    for (int r = 0; r < SHORTL; r++) {
        float cv = (head < SHORTL) ? lv[head] : INFINITY;
        int   ci = (head < SHORTL) ? li[head] : 0x7fffffff;
        float bv = cv; int bi = ci; int bl = lane;
        #pragma unroll
        for (int o = 16; o > 0; o >>= 1) {
            float ov = __shfl_down_sync(FULL, bv, o);
            int oi = __shfl_down_sync(FULL, bi, o);
            int ol = __shfl_down_sync(FULL, bl, o);
            if (ov < bv || (ov == bv && oi < bi)) { bv = ov; bi = oi; bl = ol; }
        }
        bi = __shfl_sync(FULL, bi, 0);
        bl = __shfl_sync(FULL, bl, 0);
        if (lane == r) seli = bi;
        if (lane == bl) head++;
    }

    float x2 = g_x2[row];
    const float4* xr = (const float4*)(X + (size_t)row * DIM);
    float4 xa = xr[lane * 2], xb = xr[lane * 2 + 1];
    float my_dist = INFINITY;
    for (int cc = 0; cc < SHORTL; cc++) {
        int ci = __shfl_sync(FULL, seli, cc);
        float dist = INFINITY;
        if (ci >= 0 && ci < NLEAF) {
            const float4* yr = (const float4*)(Y + (size_t)ci * DIM);
            float4 ya = yr[lane * 2], yb = yr[lane * 2 + 1];
            float s = xa.x*ya.x + xa.y*ya.y + xa.z*ya.z + xa.w*ya.w
                    + xb.x*yb.x + xb.y*yb.y + xb.z*yb.z + xb.w*yb.w;
            #pragma unroll
            for (int o = 16; o > 0; o >>= 1) s += __shfl_down_sync(FULL, s, o);
            s = __shfl_sync(FULL, s, 0);
            float y2 = g_y2[ci];
            float sq    = fmaxf(x2 + y2 - 2.0f * s, 0.0f);
            float denom = fmaxf((1.0f - x2) * (1.0f - y2), EPSF);
            float arg   = fmaxf(1.0f + 2.0f * sq / denom, 1.0f + EPSF);
            dist = acoshf(arg);
        } else ci = -1;
        if (lane == cc) { my_dist = dist; seli = ci; }
    }

    float dall[SHORTL]; int iall[SHORTL];
    for (int cc = 0; cc < SHORTL; cc++) {
        dall[cc] = __shfl_sync(FULL, my_dist, cc);
        iall[cc] = __shfl_sync(FULL, seli, cc);
    }
    for (int a2 = 1; a2 < SHORTL; a2++) {
        float dv = dall[a2]; int iv = iall[a2];
        int p = a2;
        while (p > 0 && (dall[p-1] > dv || (dall[p-1] == dv && iall[p-1] > iv))) {
            dall[p] = dall[p-1]; iall[p] = iall[p-1]; p--;
        }
        dall[p] = dv; iall[p] = iv;
    }

    if (lane == 0) {
        float score = dall[0];
        out[row] = score;
        if (out_size >= 2 * BATCH)
            out[BATCH + row] = (score > thr_p[0]) ? 1.0f : 0.0f;
        if (out_size >= 7 * BATCH) {
            #pragma unroll
            for (int j = 0; j < 5; j++) {
                int ci = iall[j];
                out[2 * BATCH + (size_t)row * 5 + j] = (float)((ci >= 0) ? ids[ci] : 0);
            }
        }
    }
}

// ---------------------------------------------------------------------------
extern "C" void kernel_launch(void* const* d_in, const int* in_sizes, int n_in,
                              void* d_out, int out_size) {
    const float* X   = (const float*)d_in[0];
    const float* Y   = (const float*)d_in[1];
    const int*   ids = (const int*)d_in[2];
    const float* thr = (const float*)d_in[3];
    float* out = (float*)d_out;

    cudaFuncSetAttribute(main_kernel, cudaFuncAttributeMaxDynamicSharedMemorySize,
                         SMEM_TOTAL);

    int prep_warps = BATCH + NLEAF;
    prep_kernel<<<(prep_warps + 7) / 8, 256>>>(X, Y);

    main_kernel<<<dim3(BATCH / 128, NCHUNK), 128, SMEM_TOTAL>>>();

    merge_kernel<<<BATCH / 8, 256>>>(X, Y, ids, thr, out, out_size);
}

// round 5
// speedup vs baseline: 5.0082x; 1.0342x over previous
#include <cuda_runtime.h>
#include <cuda_bf16.h>
#include <cstdint>
#include <math.h>

#define BATCH   4096
#define NLEAF   50000
#define DIM     256
#define KPAD    288                 // 256 dims + 2 aug + zero pad (18 ksteps of 16)
#define CHUNKL  5556
#define NCHUNK  9
#define NTILES  44                  // tiles of 128 leaves per chunk
#define EPSF    1e-7f
#define SHORTL  16
#define NSLOT   5
#define NCANDR  (NCHUNK * NSLOT * 2) // 90 candidates per row (2 half-row lists)

// smem: 2 stages of {Ahi,Alo,Bhi,Blo}, each mat 128 rows x 112B.
// f32 dump buffer OVERLAYS the stages (stages are dead when dump happens).
#define PITCHB   112
#define MATB     (128 * PITCHB)     // 14336
#define OFF_ALO  MATB
#define OFF_BHI  (2 * MATB)
#define OFF_BLO  (3 * MATB)
#define STAGEB   (4 * MATB)         // 57344
#define DPITCH   132                // floats
#define SMEM_TOTAL (2 * STAGEB)     // 114688 >= dump (128*132*4 = 67584)

__device__ float g_x2[BATCH];
__device__ float g_y2[NLEAF];
__device__ __align__(16) __nv_bfloat16 g_Xh[(size_t)BATCH * KPAD];
__device__ __align__(16) __nv_bfloat16 g_Xl[(size_t)BATCH * KPAD];
__device__ __align__(16) __nv_bfloat16 g_Yh[(size_t)NLEAF * KPAD];
__device__ __align__(16) __nv_bfloat16 g_Yl[(size_t)NLEAF * KPAD];
__device__ float g_cval[(size_t)NCHUNK * BATCH * NSLOT * 2];
__device__ int   g_cidx[(size_t)NCHUNK * BATCH * NSLOT * 2];

__device__ __forceinline__ uint32_t smem_to_u32(const void* p) {
    uint32_t a;
    asm("{ .reg .u64 t; cvta.to.shared.u64 t, %1; cvt.u32.u64 %0, t; }" : "=r"(a) : "l"(p));
    return a;
}
#define LDSM_X4(r0, r1, r2, r3, addr) \
    asm volatile("ldmatrix.sync.aligned.m8n8.x4.shared.b16 {%0,%1,%2,%3}, [%4];" \
        : "=r"(r0), "=r"(r1), "=r"(r2), "=r"(r3) : "r"(addr))
#define MMA16816(c, a, b0, b1) \
    asm volatile("mma.sync.aligned.m16n8k16.row.col.f32.bf16.bf16.f32 " \
        "{%0,%1,%2,%3},{%4,%5,%6,%7},{%8,%9},{%0,%1,%2,%3};" \
        : "+f"((c)[0]), "+f"((c)[1]), "+f"((c)[2]), "+f"((c)[3]) \
        : "r"((a)[0]), "r"((a)[1]), "r"((a)[2]), "r"((a)[3]), "r"(b0), "r"(b1))
#define CP_WAIT(n) asm volatile("cp.async.wait_group %0;" :: "n"(n) : "memory")

__device__ __forceinline__ unsigned bfu(__nv_bfloat16 h) {
    return (unsigned)__bfloat16_as_ushort(h);
}

// ---------------- Kernel 1: norms + bf16 hi/lo split of augmented rows ----
// x' = [x, x2, 1, 0pad];  y' = [-2*inv*y, inv, y2*inv, 0pad], inv=1/(1-y2)
// => dot(x', y') = (x2 + y2 - 2 x.y)/(1 - y2): monotone hyperbolic-dist key.
__global__ void prep_kernel(const float* __restrict__ X, const float* __restrict__ Y) {
    int warp = (blockIdx.x * blockDim.x + threadIdx.x) >> 5;
    int lane = threadIdx.x & 31;
    if (warp >= BATCH + NLEAF) return;
    bool isX = warp < BATCH;
    int row = isX ? warp : warp - BATCH;
    const float* src = (isX ? X : Y) + (size_t)row * DIM;
    float4 a = ((const float4*)src)[lane * 2];
    float4 b = ((const float4*)src)[lane * 2 + 1];
    float v[8] = {a.x, a.y, a.z, a.w, b.x, b.y, b.z, b.w};
    float s = 0.0f;
    #pragma unroll
    for (int i = 0; i < 8; i++) s += v[i] * v[i];
    #pragma unroll
    for (int o = 16; o; o >>= 1) s += __shfl_xor_sync(0xffffffffu, s, o);

    float scale, aug0, aug1;
    __nv_bfloat16 *dh, *dl;
    if (isX) {
        if (lane == 0) g_x2[row] = s;
        scale = 1.0f; aug0 = s; aug1 = 1.0f;
        dh = g_Xh + (size_t)row * KPAD; dl = g_Xl + (size_t)row * KPAD;
    } else {
        float inv = 1.0f / (1.0f - s);
        if (lane == 0) g_y2[row] = s;
        scale = -2.0f * inv; aug0 = inv; aug1 = s * inv;
        dh = g_Yh + (size_t)row * KPAD; dl = g_Yl + (size_t)row * KPAD;
    }
    unsigned hw[4], lw[4];
    #pragma unroll
    for (int i = 0; i < 4; i++) {
        float w0 = v[2*i] * scale, w1 = v[2*i+1] * scale;
        __nv_bfloat16 h0 = __float2bfloat16(w0), h1 = __float2bfloat16(w1);
        float r0 = w0 - __bfloat162float(h0), r1 = w1 - __bfloat162float(h1);
        hw[i] = bfu(h0) | (bfu(h1) << 16);
        lw[i] = bfu(__float2bfloat16(r0)) | (bfu(__float2bfloat16(r1)) << 16);
    }
    ((uint4*)dh)[lane] = make_uint4(hw[0], hw[1], hw[2], hw[3]);
    ((uint4*)dl)[lane] = make_uint4(lw[0], lw[1], lw[2], lw[3]);
    if (lane == 0) {
        __nv_bfloat16 h0 = __float2bfloat16(aug0), h1 = __float2bfloat16(aug1);
        float r0 = aug0 - __bfloat162float(h0), r1 = aug1 - __bfloat162float(h1);
        uint4 z = make_uint4(0, 0, 0, 0);
        ((uint4*)dh)[32] = make_uint4(bfu(h0) | (bfu(h1) << 16), 0, 0, 0);
        ((uint4*)dl)[32] = make_uint4(bfu(__float2bfloat16(r0)) | (bfu(__float2bfloat16(r1)) << 16), 0, 0, 0);
        #pragma unroll
        for (int q = 33; q < 36; q++) { ((uint4*)dh)[q] = z; ((uint4*)dl)[q] = z; }
    }
}

// cp.async one k-chunk (48 k-elems) of Ahi/Alo/Bhi/Blo into one smem stage.
// 256 threads, 3072 16B transfers, 12 per thread; each i-block stays in 1 mat.
__device__ __forceinline__ void issue_loads(uint32_t stg, int tid, int mrow0,
                                            int leaf0, int kc) {
    const int k0 = kc * 48;
    #pragma unroll
    for (int i = 0; i < 12; i++) {
        int u = tid + 256 * i;
        int mat = u / 768;
        int rem = u - mat * 768;
        int row = rem / 6;
        int col = rem - row * 6;
        uint32_t dst = stg + (uint32_t)mat * MATB + (uint32_t)row * PITCHB
                     + (uint32_t)col * 16;
        const __nv_bfloat16* src;
        if (mat < 2) {
            src = (mat == 0 ? g_Xh : g_Xl) + (size_t)(mrow0 + row) * KPAD + k0 + col * 8;
        } else {
            int leaf = leaf0 + row; if (leaf >= NLEAF) leaf = NLEAF - 1;
            src = (mat == 2 ? g_Yh : g_Yl) + (size_t)leaf * KPAD + k0 + col * 8;
        }
        asm volatile("cp.async.cg.shared.global [%0], [%1], 16;"
                     :: "r"(dst), "l"(src) : "memory");
    }
    asm volatile("cp.async.commit_group;" ::: "memory");
}

// ---------------- Kernel 2: bf16x3 mma.sync GEMM + fused exact top-5 ------
// 256 threads = 8 warps (2m x 4n), warp tile 64x32, block tile 128x128.
__global__ void __launch_bounds__(256, 2) main_kernel() {
    extern __shared__ char smem[];
    const uint32_t sb = smem_to_u32(smem);
    const int tid = threadIdx.x, lane = tid & 31, w = tid >> 5;
    const int wm = w >> 2, wn = w & 3;
    const int mblk = blockIdx.x, chunk = blockIdx.y;
    const int mrow0 = mblk * 128;
    const int leaf_base = chunk * CHUNKL;
    int leaf_end = leaf_base + CHUNKL; if (leaf_end > NLEAF) leaf_end = NLEAF;

    const uint32_t aoff = (uint32_t)(wm * 64 + (lane & 15)) * PITCHB
                        + ((lane >> 4) & 1) * 16;
    const uint32_t boff = (uint32_t)(wn * 32 + (lane & 7) + ((lane >> 4) & 1) * 8) * PITCHB
                        + ((lane >> 3) & 1) * 16;

    float tv[NSLOT]; int ti[NSLOT];
    #pragma unroll
    for (int q = 0; q < NSLOT; q++) { tv[q] = INFINITY; ti[q] = -1; }

    for (int t = 0; t < NTILES; t++) {
        const int leaf0 = leaf_base + t * 128;
        issue_loads(sb, tid, mrow0, leaf0, 0);

        float c[4][4][4];
        #pragma unroll
        for (int mi = 0; mi < 4; mi++)
            #pragma unroll
            for (int ni = 0; ni < 4; ni++)
                #pragma unroll
                for (int e = 0; e < 4; e++) c[mi][ni][e] = 0.0f;

        for (int kc = 0; kc < 6; kc++) {
            const uint32_t stg = sb + (uint32_t)(kc & 1) * STAGEB;
            if (kc < 5) {
                issue_loads(sb + (uint32_t)((kc + 1) & 1) * STAGEB, tid, mrow0, leaf0, kc + 1);
                CP_WAIT(1);
            } else {
                CP_WAIT(0);
            }
            __syncthreads();

            #pragma unroll
            for (int pass = 0; pass < 3; pass++) {
                const uint32_t Ab = stg + (pass == 2 ? OFF_ALO : 0u) + aoff;
                const uint32_t Bb = stg + (pass == 1 ? (uint32_t)OFF_BLO : (uint32_t)OFF_BHI) + boff;
                #pragma unroll
                for (int ks = 0; ks < 3; ks++) {
                    uint32_t a[4][4];
                    #pragma unroll
                    for (int mi = 0; mi < 4; mi++)
                        LDSM_X4(a[mi][0], a[mi][1], a[mi][2], a[mi][3],
                                Ab + mi * (16 * PITCHB) + ks * 32);
                    #pragma unroll
                    for (int nj = 0; nj < 2; nj++) {
                        uint32_t b[4];
                        LDSM_X4(b[0], b[1], b[2], b[3],
                                Bb + nj * (16 * PITCHB) + ks * 32);
                        #pragma unroll
                        for (int mi = 0; mi < 4; mi++) {
                            MMA16816(c[mi][2 * nj],     a[mi], b[0], b[1]);
                            MMA16816(c[mi][2 * nj + 1], a[mi], b[2], b[3]);
                        }
                    }
                }
            }
            __syncthreads();
        }

        // dump accum (128x128 f32) into smem (overlays dead stage buffers)
        {
            const int r0 = wm * 64 + (lane >> 2);
            const int c0 = wn * 32 + 2 * (lane & 3);
            #pragma unroll
            for (int mi = 0; mi < 4; mi++) {
                #pragma unroll
                for (int ni = 0; ni < 4; ni++) {
                    uint32_t a0 = sb + (uint32_t)((r0 + mi * 16) * DPITCH + c0 + ni * 8) * 4;
                    asm volatile("st.shared.v2.f32 [%0], {%1,%2};"
                                 :: "r"(a0), "f"(c[mi][ni][0]), "f"(c[mi][ni][1]) : "memory");
                    asm volatile("st.shared.v2.f32 [%0], {%1,%2};"
                                 :: "r"(a0 + 8 * DPITCH * 4), "f"(c[mi][ni][2]), "f"(c[mi][ni][3]) : "memory");
                }
            }
        }
        __syncthreads();
        // thread owns (row = tid&127, half = tid>>7): exact top-5 over 64 cols
        {
            const int half = tid >> 7;
            int nvalid = leaf_end - leaf0; if (nvalid > 128) nvalid = 128;
            const uint32_t rb = sb + (uint32_t)(tid & 127) * (DPITCH * 4) + half * 256;
            #pragma unroll 4
            for (int j4 = 0; j4 < 16; j4++) {
                float v0, v1, v2, v3;
                asm volatile("ld.shared.v4.f32 {%0,%1,%2,%3}, [%4];"
                             : "=f"(v0), "=f"(v1), "=f"(v2), "=f"(v3)
                             : "r"(rb + j4 * 16));
                float vv[4] = {v0, v1, v2, v3};
                #pragma unroll
                for (int e = 0; e < 4; e++) {
                    int col = half * 64 + j4 * 4 + e;
                    float key = fmaxf(vv[e], 0.0f);
                    if (col < nvalid && key < tv[4]) {
                        tv[4] = key; ti[4] = leaf0 + col;
                        #pragma unroll
                        for (int q = 4; q > 0; q--) {
                            if (tv[q] < tv[q - 1]) {
                                float fv = tv[q]; tv[q] = tv[q - 1]; tv[q - 1] = fv;
                                int iv = ti[q]; ti[q] = ti[q - 1]; ti[q - 1] = iv;
                            }
                        }
                    }
                }
            }
        }
        __syncthreads();
    }

    const int grow = mrow0 + (tid & 127);
    const size_t cb = (((size_t)chunk * BATCH + grow) * 2 + (tid >> 7)) * NSLOT;
    #pragma unroll
    for (int q = 0; q < NSLOT; q++) { g_cval[cb + q] = tv[q]; g_cidx[cb + q] = ti[q]; }
}

// ---------------- Kernel 3: merge 90 cands -> top-16, exact re-rank -------
__global__ void merge_kernel(const float* __restrict__ X, const float* __restrict__ Y,
                             const int* __restrict__ ids, const float* __restrict__ thr_p,
                             float* __restrict__ out, int out_size) {
    const int lane = threadIdx.x & 31;
    const int row = blockIdx.x * 8 + (threadIdx.x >> 5);
    if (row >= BATCH) return;
    const unsigned FULL = 0xffffffffu;

    float lv[SHORTL]; int li[SHORTL];
    #pragma unroll
    for (int s = 0; s < SHORTL; s++) { lv[s] = INFINITY; li[s] = 0x7fffffff; }
    for (int f = lane; f < NCANDR; f += 32) {
        int ch = f / 10, r = f - ch * 10;
        size_t a = ((size_t)ch * BATCH + row) * 10 + r;
        float v = g_cval[a];
        if (v < lv[SHORTL - 1]) {
            int ix = g_cidx[a];
            if (ix < 0) continue;
            int p = SHORTL - 1;
            while (p > 0 && (lv[p-1] > v || (lv[p-1] == v && li[p-1] > ix))) {
                lv[p] = lv[p-1]; li[p] = li[p-1]; p--;
            }
            lv[p] = v; li[p] = ix;
        }
    }

    int head = 0, seli = -1;
    for (int r = 0; r < SHORTL; r++) {
        float cv = (head < SHORTL) ? lv[head] : INFINITY;
        int   ci = (head < SHORTL) ? li[head] : 0x7fffffff;
        float bv = cv; int bi = ci; int bl = lane;
        #pragma unroll
        for (int o = 16; o > 0; o >>= 1) {
            float ov = __shfl_down_sync(FULL, bv, o);
            int oi = __shfl_down_sync(FULL, bi, o);
            int ol = __shfl_down_sync(FULL, bl, o);
            if (ov < bv || (ov == bv && oi < bi)) { bv = ov; bi = oi; bl = ol; }
        }
        bi = __shfl_sync(FULL, bi, 0);
        bl = __shfl_sync(FULL, bl, 0);
        if (lane == r) seli = bi;
        if (lane == bl) head++;
    }

    float x2 = g_x2[row];
    const float4* xr = (const float4*)(X + (size_t)row * DIM);
    float4 xa = xr[lane * 2], xb = xr[lane * 2 + 1];
    float my_dist = INFINITY;
    for (int cc = 0; cc < SHORTL; cc++) {
        int ci = __shfl_sync(FULL, seli, cc);
        float dist = INFINITY;
        if (ci >= 0 && ci < NLEAF) {
            const float4* yr = (const float4*)(Y + (size_t)ci * DIM);
            float4 ya = yr[lane * 2], yb = yr[lane * 2 + 1];
            float s = xa.x*ya.x + xa.y*ya.y + xa.z*ya.z + xa.w*ya.w
                    + xb.x*yb.x + xb.y*yb.y + xb.z*yb.z + xb.w*yb.w;
            #pragma unroll
            for (int o = 16; o > 0; o >>= 1) s += __shfl_down_sync(FULL, s, o);
            s = __shfl_sync(FULL, s, 0);
            float y2 = g_y2[ci];
            float sq    = fmaxf(x2 + y2 - 2.0f * s, 0.0f);
            float denom = fmaxf((1.0f - x2) * (1.0f - y2), EPSF);
            float arg   = fmaxf(1.0f + 2.0f * sq / denom, 1.0f + EPSF);
            dist = acoshf(arg);
        } else ci = -1;
        if (lane == cc) { my_dist = dist; seli = ci; }
    }

    float dall[SHORTL]; int iall[SHORTL];
    for (int cc = 0; cc < SHORTL; cc++) {
        dall[cc] = __shfl_sync(FULL, my_dist, cc);
        iall[cc] = __shfl_sync(FULL, seli, cc);
    }
    for (int a2 = 1; a2 < SHORTL; a2++) {
        float dv = dall[a2]; int iv = iall[a2];
        int p = a2;
        while (p > 0 && (dall[p-1] > dv || (dall[p-1] == dv && iall[p-1] > iv))) {
            dall[p] = dall[p-1]; iall[p] = iall[p-1]; p--;
        }
        dall[p] = dv; iall[p] = iv;
    }

    if (lane == 0) {
        float score = dall[0];
        out[row] = score;
        if (out_size >= 2 * BATCH)
            out[BATCH + row] = (score > thr_p[0]) ? 1.0f : 0.0f;
        if (out_size >= 7 * BATCH) {
            #pragma unroll
            for (int j = 0; j < 5; j++) {
                int ci = iall[j];
                out[2 * BATCH + (size_t)row * 5 + j] = (float)((ci >= 0) ? ids[ci] : 0);
            }
        }
    }
}

// ---------------------------------------------------------------------------
extern "C" void kernel_launch(void* const* d_in, const int* in_sizes, int n_in,
                              void* d_out, int out_size) {
    const float* X   = (const float*)d_in[0];
    const float* Y   = (const float*)d_in[1];
    const int*   ids = (const int*)d_in[2];
    const float* thr = (const float*)d_in[3];
    float* out = (float*)d_out;

    cudaFuncSetAttribute(main_kernel, cudaFuncAttributeMaxDynamicSharedMemorySize,
                         SMEM_TOTAL);

    int prep_warps = BATCH + NLEAF;
    prep_kernel<<<(prep_warps + 7) / 8, 256>>>(X, Y);

    main_kernel<<<dim3(BATCH / 128, NCHUNK), 256, SMEM_TOTAL>>>();

    merge_kernel<<<BATCH / 8, 256>>>(X, Y, ids, thr, out, out_size);
}